// round 14
// baseline (speedup 1.0000x reference)
#include <cuda_runtime.h>
#include <cuda_bf16.h>
#include <math.h>
#include <cstdint>

// Problem constants
#define BZ 2
#define TT 2048
#define EE 4096
#define HQ 32
#define HKV 8
#define DD 128
#define GG 4
#define MM (BZ * TT)          // 4096 rows
#define KVE (HKV * DD)        // 1024

// ---------------- scratch (no cudaMalloc allowed) ----------------
__device__ float g_Q[(size_t)MM * EE];    // 64 MB  (B,T,HQ,D)
__device__ float g_K[(size_t)MM * KVE];   // 16 MB  (B,T,HKV,D)
__device__ float g_V[(size_t)MM * KVE];   // 16 MB
__device__ float g_Y[(size_t)MM * EE];    // 64 MB  attention output (B,T,HQ,D)

__device__ __forceinline__ uint32_t f2tf32(float f) {
    uint32_t r;
    asm("cvt.rna.tf32.f32 %0, %1;" : "=r"(r) : "f"(f));
    return r;
}
__device__ __forceinline__ uint32_t smem_u32(const void* p) {
    uint32_t a;
    asm("{ .reg .u64 t; cvta.to.shared.u64 t, %1; cvt.u32.u64 %0, t; }" : "=r"(a) : "l"(p));
    return a;
}
__device__ __forceinline__ void cp16(uint32_t dst, const float* src) {
    asm volatile("cp.async.cg.shared.global [%0], [%1], 16;" :: "r"(dst), "l"(src) : "memory");
}
#define CP_COMMIT() asm volatile("cp.async.commit_group;" ::: "memory")
#define CP_WAIT1()  asm volatile("cp.async.wait_group 1;" ::: "memory")

// tf32 warp MMA: D(16x8) += A(16x8) * B(8x8)
__device__ __forceinline__ void mma_tf32(float* c,
                                         uint32_t a0, uint32_t a1, uint32_t a2, uint32_t a3,
                                         uint32_t b0, uint32_t b1) {
    asm volatile(
        "mma.sync.aligned.m16n8k8.row.col.f32.tf32.tf32.f32 "
        "{%0,%1,%2,%3}, {%4,%5,%6,%7}, {%8,%9}, {%0,%1,%2,%3};"
        : "+f"(c[0]), "+f"(c[1]), "+f"(c[2]), "+f"(c[3])
        : "r"(a0), "r"(a1), "r"(a2), "r"(a3), "r"(b0), "r"(b1));
}

// =================== tf32 mma.sync GEMM (BK=32, 3-stage cp.async pipeline) ===================
// C[m,n] = sum_k A[m,k]*B[n,k] + bias[n]; A (M,K), B (N,K) row-major fp32
// Block 128x128x32, 8 warps, warp tile 64x32. SMEM raw fp32 m-major, rows padded
// to 36 floats: fragment banks (4r + c) mod 32 conflict-free.
#define BM 128
#define BN 128
#define BK 32
#define ROWF 36
#define HALF_STAGE (128 * ROWF)             // floats (A part)
#define STAGE_FLOATS (2 * HALF_STAGE)       // A then B
#define NSTAGE 3
#define GEMM_SMEM_BYTES (NSTAGE * STAGE_FLOATS * 4)   // 110592

__global__ __launch_bounds__(256) void gemm_mma_kernel(
    const float* __restrict__ A, const float* __restrict__ Bm,
    const float* __restrict__ bias, float* __restrict__ C,
    int M, int N, int K)
{
    extern __shared__ float smem[];
    const uint32_t smem_base = smem_u32(smem);

    const int tid = threadIdx.x;
    const int wid = tid >> 5;
    const int lane = tid & 31;
    const int bm = blockIdx.y * BM;
    const int bn = blockIdx.x * BN;

    const int warp_m = (wid >> 2) * 64;
    const int warp_n = (wid & 3) * 32;
    const int lq = lane >> 2;
    const int lr = lane & 3;

    float acc[4][4][4];
#pragma unroll
    for (int i = 0; i < 4; i++)
#pragma unroll
        for (int j = 0; j < 4; j++)
#pragma unroll
            for (int r = 0; r < 4; r++) acc[i][j][r] = 0.f;

    // copy mapping: per stage each matrix = 128 rows x 8 chunks(16B) = 1024 chunks;
    // thread does 4 consecutive chunks = one row-half: row = tid>>1, kq base = (tid&1)*4
    const int crow = tid >> 1;
    const int kqb  = (tid & 1) * 4;
    const float* Arow = A + (size_t)(bm + crow) * K + kqb * 4;
    const float* Brow = Bm + (size_t)(bn + crow) * K + kqb * 4;
    const uint32_t s_off = (uint32_t)(crow * ROWF + kqb * 4) * 4;

    const int NK = K / BK;

#define ISSUE_STAGE(it, slot) do {                                           \
        uint32_t sbase = smem_base + (uint32_t)(slot) * (STAGE_FLOATS * 4) + s_off; \
        uint32_t bbase = sbase + HALF_STAGE * 4;                             \
        const float* ap = Arow + (it) * BK;                                  \
        const float* bp = Brow + (it) * BK;                                  \
        cp16(sbase,      ap);                                                \
        cp16(sbase + 16, ap + 4);                                            \
        cp16(sbase + 32, ap + 8);                                            \
        cp16(sbase + 48, ap + 12);                                           \
        cp16(bbase,      bp);                                                \
        cp16(bbase + 16, bp + 4);                                            \
        cp16(bbase + 32, bp + 8);                                            \
        cp16(bbase + 48, bp + 12);                                           \
    } while (0)

    // prologue: stages 0,1 in flight
#pragma unroll
    for (int s = 0; s < NSTAGE - 1; s++) {
        if (s < NK) ISSUE_STAGE(s, s);
        CP_COMMIT();
    }

    for (int it = 0; it < NK; it++) {
        CP_WAIT1();            // stage it arrived (<=1 group pending)
        __syncthreads();       // all warps done with slot (it-1)%3; safe to reuse

        int nxt = it + NSTAGE - 1;
        if (nxt < NK) ISSUE_STAGE(nxt, nxt % NSTAGE);
        CP_COMMIT();

        const float* sa = smem + (it % NSTAGE) * STAGE_FLOATS;
        const float* sb = sa + HALF_STAGE;

#pragma unroll
        for (int ks = 0; ks < BK; ks += 8) {
            uint32_t af[4][4];
#pragma unroll
            for (int mt = 0; mt < 4; mt++) {
                int r = warp_m + mt * 16 + lq;
                int c = ks + lr;
                af[mt][0] = f2tf32(sa[r * ROWF + c]);
                af[mt][1] = f2tf32(sa[(r + 8) * ROWF + c]);
                af[mt][2] = f2tf32(sa[r * ROWF + c + 4]);
                af[mt][3] = f2tf32(sa[(r + 8) * ROWF + c + 4]);
            }
            uint32_t bf[4][2];
#pragma unroll
            for (int nt = 0; nt < 4; nt++) {
                int n = warp_n + nt * 8 + lq;
                int k = ks + lr;
                bf[nt][0] = f2tf32(sb[n * ROWF + k]);
                bf[nt][1] = f2tf32(sb[n * ROWF + k + 4]);
            }
#pragma unroll
            for (int mt = 0; mt < 4; mt++)
#pragma unroll
                for (int nt = 0; nt < 4; nt++)
                    mma_tf32(acc[mt][nt], af[mt][0], af[mt][1], af[mt][2], af[mt][3],
                             bf[nt][0], bf[nt][1]);
        }
    }

    // epilogue: frag layout c0=(r, 2c) c1=(r, 2c+1) c2=(r+8, 2c) c3=(r+8, 2c+1)
#pragma unroll
    for (int mt = 0; mt < 4; mt++) {
#pragma unroll
        for (int nt = 0; nt < 4; nt++) {
            int r0 = bm + warp_m + mt * 16 + lq;
            int c0 = bn + warp_n + nt * 8 + lr * 2;
            float bvx = bias[c0], bvy = bias[c0 + 1];
            float2 v0 = make_float2(acc[mt][nt][0] + bvx, acc[mt][nt][1] + bvy);
            float2 v1 = make_float2(acc[mt][nt][2] + bvx, acc[mt][nt][3] + bvy);
            *(float2*)(C + (size_t)r0 * N + c0) = v0;
            *(float2*)(C + (size_t)(r0 + 8) * N + c0) = v1;
        }
    }
#undef ISSUE_STAGE
}

// ---------------- RoPE (in-place) ----------------
__global__ void rope_kernel(float* __restrict__ X, const float* __restrict__ fr, int H)
{
    int idx = blockIdx.x * blockDim.x + threadIdx.x;
    int total = BZ * TT * H * (DD / 2);
    if (idx >= total) return;
    int j = idx % (DD / 2);
    int h = (idx / (DD / 2)) % H;
    int t = (idx / ((DD / 2) * H)) % TT;
    int b = idx / ((DD / 2) * H * TT);
    float c = fr[(t * (DD / 2) + j) * 2 + 0];
    float s = fr[(t * (DD / 2) + j) * 2 + 1];
    size_t base = (((size_t)b * TT + t) * H + h) * DD + 2 * j;
    float x0 = X[base], x1 = X[base + 1];
    X[base]     = x0 * c - x1 * s;
    X[base + 1] = x1 * c + x0 * s;
}

// ---------------- Flash attention (causal, GQA, tf32 mma + parallel softmax) ----------------
#define BQ 64
#define BKT 64
#define QSTR 136
#define SSTR 68
#define FLASH_SMEM_FLOATS (3 * BQ * QSTR + BQ * SSTR + 3 * BQ)
#define FLASH_SMEM_BYTES (FLASH_SMEM_FLOATS * 4)   // 122624

__global__ __launch_bounds__(256) void flash_attn_kernel(
    const float* __restrict__ Q, const float* __restrict__ K,
    const float* __restrict__ V, float* __restrict__ Y)
{
    extern __shared__ float sm[];
    float* Qs = sm;                       // [64][136]
    float* Ks = Qs + BQ * QSTR;           // [64][136]
    float* Vs = Ks + BKT * QSTR;          // [64][136]
    float* Ss = Vs + BKT * QSTR;          // [64][68]
    float* fac  = Ss + BQ * SSTR;
    float* mrow = fac + BQ;
    float* lrow = mrow + BQ;

    const int tid = threadIdx.x;
    const int wid = tid >> 5;
    const int lane = tid & 31;
    const int lq = lane >> 2;     // 0..7
    const int lr = lane & 3;      // 0..3

    const int r0  = (wid >> 1) * 16;   // warp's S/O row base (0,16,32,48)
    const int c0  = (wid & 1) * 32;    // warp's S col base  (0,32)
    const int oc0 = (wid & 1) * 64;    // warp's O col base  (0,64)

    const int q0 = blockIdx.x * BQ;
    const int h  = blockIdx.y;
    const int b  = blockIdx.z;
    const int hk = h / GG;
    const float scale = rsqrtf((float)DD);

    // load Q tile
    for (int i = tid; i < BQ * (DD / 4); i += 256) {
        int r = i >> 5;
        int c4 = (i & 31) * 4;
        float4 v = *(const float4*)(Q + ((((size_t)b * TT + q0 + r) * HQ + h) * DD + c4));
        *(float4*)(Qs + r * QSTR + c4) = v;
    }
    if (tid < BQ) { mrow[tid] = -1e30f; lrow[tid] = 0.f; }

    float oacc[8][4];
#pragma unroll
    for (int nt = 0; nt < 8; nt++)
#pragma unroll
        for (int r = 0; r < 4; r++) oacc[nt][r] = 0.f;

    const int ktiles = q0 / BKT + 1;
    for (int kt = 0; kt < ktiles; kt++) {
        const int k0 = kt * BKT;
        __syncthreads();
        for (int i = tid; i < BKT * (DD / 4); i += 256) {
            int r = i >> 5;
            int c4 = (i & 31) * 4;
            size_t gidx = (((size_t)b * TT + k0 + r) * HKV + hk) * DD + c4;
            *(float4*)(Ks + r * QSTR + c4) = *(const float4*)(K + gidx);
            *(float4*)(Vs + r * QSTR + c4) = *(const float4*)(V + gidx);
        }
        __syncthreads();

        // ---- S = Q K^T (tf32 mma) ----
        float sacc[4][4];
#pragma unroll
        for (int nt = 0; nt < 4; nt++)
#pragma unroll
            for (int r = 0; r < 4; r++) sacc[nt][r] = 0.f;

#pragma unroll
        for (int d = 0; d < DD; d += 8) {
            uint32_t a0 = f2tf32(Qs[(r0 + lq) * QSTR + d + lr]);
            uint32_t a1 = f2tf32(Qs[(r0 + lq + 8) * QSTR + d + lr]);
            uint32_t a2 = f2tf32(Qs[(r0 + lq) * QSTR + d + lr + 4]);
            uint32_t a3 = f2tf32(Qs[(r0 + lq + 8) * QSTR + d + lr + 4]);
#pragma unroll
            for (int nt = 0; nt < 4; nt++) {
                uint32_t b0 = f2tf32(Ks[(c0 + nt * 8 + lq) * QSTR + d + lr]);
                uint32_t b1 = f2tf32(Ks[(c0 + nt * 8 + lq) * QSTR + d + lr + 4]);
                mma_tf32(sacc[nt], a0, a1, a2, a3, b0, b1);
            }
        }
        // scale + causal mask + store to Ss
#pragma unroll
        for (int nt = 0; nt < 4; nt++) {
            int c = c0 + nt * 8 + lr * 2;
            int r = r0 + lq;
            float v0 = sacc[nt][0] * scale, v1 = sacc[nt][1] * scale;
            float v2 = sacc[nt][2] * scale, v3 = sacc[nt][3] * scale;
            if (k0 + c     > q0 + r)     v0 = -1e30f;
            if (k0 + c + 1 > q0 + r)     v1 = -1e30f;
            if (k0 + c     > q0 + r + 8) v2 = -1e30f;
            if (k0 + c + 1 > q0 + r + 8) v3 = -1e30f;
            *(float2*)(Ss + r * SSTR + c) = make_float2(v0, v1);
            *(float2*)(Ss + (r + 8) * SSTR + c) = make_float2(v2, v3);
        }
        __syncthreads();

        // ---- online softmax: 4 threads per row ----
        {
            int r = tid >> 2;
            int sub = tid & 3;
            float* row = Ss + r * SSTR + sub * 16;
            float mo = mrow[r];
            float mx = mo;
            float vals[16];
#pragma unroll
            for (int i = 0; i < 16; i++) { vals[i] = row[i]; mx = fmaxf(mx, vals[i]); }
            mx = fmaxf(mx, __shfl_xor_sync(0xFFFFFFFFu, mx, 1));
            mx = fmaxf(mx, __shfl_xor_sync(0xFFFFFFFFu, mx, 2));
            float sum = 0.f;
#pragma unroll
            for (int i = 0; i < 16; i++) {
                float p = __expf(vals[i] - mx);
                row[i] = p;
                sum += p;
            }
            sum += __shfl_xor_sync(0xFFFFFFFFu, sum, 1);
            sum += __shfl_xor_sync(0xFFFFFFFFu, sum, 2);
            if (sub == 0) {
                float f = __expf(mo - mx);
                lrow[r] = lrow[r] * f + sum;
                mrow[r] = mx;
                fac[r] = f;
            }
        }
        __syncthreads();

        // ---- O = O*fac + P V (tf32 mma) ----
        {
            float f0 = fac[r0 + lq];
            float f1 = fac[r0 + lq + 8];
#pragma unroll
            for (int nt = 0; nt < 8; nt++) {
                oacc[nt][0] *= f0; oacc[nt][1] *= f0;
                oacc[nt][2] *= f1; oacc[nt][3] *= f1;
            }
        }
#pragma unroll
        for (int ks = 0; ks < BKT; ks += 8) {
            uint32_t a0 = f2tf32(Ss[(r0 + lq) * SSTR + ks + lr]);
            uint32_t a1 = f2tf32(Ss[(r0 + lq + 8) * SSTR + ks + lr]);
            uint32_t a2 = f2tf32(Ss[(r0 + lq) * SSTR + ks + lr + 4]);
            uint32_t a3 = f2tf32(Ss[(r0 + lq + 8) * SSTR + ks + lr + 4]);
#pragma unroll
            for (int nt = 0; nt < 8; nt++) {
                uint32_t b0 = f2tf32(Vs[(ks + lr) * QSTR + oc0 + nt * 8 + lq]);
                uint32_t b1 = f2tf32(Vs[(ks + lr + 4) * QSTR + oc0 + nt * 8 + lq]);
                mma_tf32(oacc[nt], a0, a1, a2, a3, b0, b1);
            }
        }
    }

    // epilogue
    {
        float inv0 = 1.f / lrow[r0 + lq];
        float inv1 = 1.f / lrow[r0 + lq + 8];
        int t0 = q0 + r0 + lq;
#pragma unroll
        for (int nt = 0; nt < 8; nt++) {
            int c = oc0 + nt * 8 + lr * 2;
            float* y0 = Y + ((((size_t)b * TT + t0) * HQ + h) * DD + c);
            float* y1 = Y + ((((size_t)b * TT + t0 + 8) * HQ + h) * DD + c);
            *(float2*)y0 = make_float2(oacc[nt][0] * inv0, oacc[nt][1] * inv0);
            *(float2*)y1 = make_float2(oacc[nt][2] * inv1, oacc[nt][3] * inv1);
        }
    }
}

// ---------------- launch ----------------
extern "C" void kernel_launch(void* const* d_in, const int* in_sizes, int n_in,
                              void* d_out, int out_size)
{
    const float* query = (const float*)d_in[0];
    const float* key   = (const float*)d_in[1];
    const float* value = (const float*)d_in[2];
    const float* freqs = (const float*)d_in[3];
    const float* Wq = (const float*)d_in[5];
    const float* bq = (const float*)d_in[6];
    const float* Wk = (const float*)d_in[7];
    const float* bk = (const float*)d_in[8];
    const float* Wv = (const float*)d_in[9];
    const float* bv = (const float*)d_in[10];
    const float* Wo = (const float*)d_in[11];
    const float* bo = (const float*)d_in[12];
    float* out = (float*)d_out;

    float *Qb, *Kb, *Vb, *Yb;
    cudaGetSymbolAddress((void**)&Qb, g_Q);
    cudaGetSymbolAddress((void**)&Kb, g_K);
    cudaGetSymbolAddress((void**)&Vb, g_V);
    cudaGetSymbolAddress((void**)&Yb, g_Y);

    cudaFuncSetAttribute(gemm_mma_kernel,
                         cudaFuncAttributeMaxDynamicSharedMemorySize, GEMM_SMEM_BYTES);
    cudaFuncSetAttribute(flash_attn_kernel,
                         cudaFuncAttributeMaxDynamicSharedMemorySize, FLASH_SMEM_BYTES);

    dim3 blk(256);
    gemm_mma_kernel<<<dim3(EE / BN, MM / BM), blk, GEMM_SMEM_BYTES>>>(query, Wq, bq, Qb, MM, EE, EE);
    gemm_mma_kernel<<<dim3(KVE / BN, MM / BM), blk, GEMM_SMEM_BYTES>>>(key,   Wk, bk, Kb, MM, KVE, EE);
    gemm_mma_kernel<<<dim3(KVE / BN, MM / BM), blk, GEMM_SMEM_BYTES>>>(value, Wv, bv, Vb, MM, KVE, EE);

    {
        int totq = BZ * TT * HQ * (DD / 2);
        rope_kernel<<<(totq + 255) / 256, 256>>>(Qb, freqs, HQ);
        int totk = BZ * TT * HKV * (DD / 2);
        rope_kernel<<<(totk + 255) / 256, 256>>>(Kb, freqs, HKV);
    }

    flash_attn_kernel<<<dim3(TT / BQ, HQ, BZ), 256, FLASH_SMEM_BYTES>>>(Qb, Kb, Vb, Yb);

    gemm_mma_kernel<<<dim3(EE / BN, MM / BM), blk, GEMM_SMEM_BYTES>>>(Yb, Wo, bo, out, MM, EE, EE);
}